// round 3
// baseline (speedup 1.0000x reference)
#include <cuda_runtime.h>
#include <math.h>

// Problem constants (match reference)
#define NN    50000
#define DH    128      // D_IN == D_HID == 128
#define S_NEI 25
#define MT    64       // rows per CTA tile
#define KC    8        // K-chunk for B double buffering
#define GRID  ((NN + MT - 1) / MT)   // 782

// ---------------- scratch (device globals; no allocation allowed) -----------
__device__ float g_h1[(size_t)NN * DH];   // relu(F @ agg1_W + b)
__device__ float g_x1[(size_t)NN * DH];   // relu(concat @ fc1_W + b) (pre-BN)
__device__ float g_xn[(size_t)NN * DH];   // post-BN, row-normalized
__device__ float g_h2[(size_t)NN * DH];   // relu(xn @ agg2_W + b)
__device__ float g_sum[DH];
__device__ float g_sq[DH];
__device__ float g_bn[2 * DH];            // [scale | shift]

// ---------------- tiny kernels ----------------------------------------------
__global__ void zero_stats_kernel(float* gsum, float* gsq) {
    gsum[threadIdx.x] = 0.f;
    gsq[threadIdx.x]  = 0.f;
}

__global__ void bn_finalize_kernel(const float* __restrict__ gsum,
                                   const float* __restrict__ gsq,
                                   const float* __restrict__ gamma,
                                   const float* __restrict__ beta,
                                   float* __restrict__ bn) {
    int c = threadIdx.x;
    const float invN = 1.f / (float)NN;
    float mean  = gsum[c] * invN;
    float var   = gsq[c] * invN - mean * mean;
    float rstd  = rsqrtf(var + 1e-5f);
    float scale = rstd * gamma[c];
    bn[c]      = scale;
    bn[DH + c] = beta[c] - mean * scale;
}

// ---------------- shared GEMM core ------------------------------------------
// Computes acc[4][8] for a MT x DH tile: rows m0..m0+63, cols 0..127.
// A (MT x KDIM) already staged in smem (row stride KDIM+4).
// B (KDIM x DH) streamed from global in KC-row chunks, double buffered.
// Contains the barrier that also publishes As (callers must NOT sync first).
template<int KDIM>
__device__ __forceinline__ void gemm_acc(const float* __restrict__ As,
                                         float* __restrict__ Bs,
                                         const float* __restrict__ W,
                                         int tid, float acc[4][8])
{
    const int tx = tid & 15, ty = tid >> 4;
    constexpr int KPAD = KDIM + 4;
    const int brow = tid >> 5;            // 0..7 : k-row within chunk
    const int bc4  = (tid & 31) << 2;     // 0..124 : column (float4)

    // stage chunk 0
    *(float4*)(Bs + brow * DH + bc4) = *(const float4*)(W + brow * DH + bc4);
    __syncthreads();   // As + Bs[0] visible

    constexpr int NKC = KDIM / KC;
    for (int kc = 0; kc < NKC; ++kc) {
        float4 nw = make_float4(0.f, 0.f, 0.f, 0.f);
        if (kc + 1 < NKC)
            nw = *(const float4*)(W + ((kc + 1) * KC + brow) * DH + bc4);

        const float* Bcur = Bs + (kc & 1) * (KC * DH);
        const float* A0   = As + (ty * 4) * KPAD + kc * KC;
#pragma unroll
        for (int kk = 0; kk < KC; ++kk) {
            float aa[4];
#pragma unroll
            for (int i = 0; i < 4; ++i) aa[i] = A0[i * KPAD + kk];
            const float* bp = Bcur + kk * DH + tx * 8;
            float4 b0 = *(const float4*)bp;
            float4 b1 = *(const float4*)(bp + 4);
            float bb[8] = {b0.x, b0.y, b0.z, b0.w, b1.x, b1.y, b1.z, b1.w};
#pragma unroll
            for (int i = 0; i < 4; ++i)
#pragma unroll
                for (int j = 0; j < 8; ++j)
                    acc[i][j] = fmaf(aa[i], bb[j], acc[i][j]);
        }
        if (kc + 1 < NKC)
            *(float4*)(Bs + ((kc + 1) & 1) * (KC * DH) + brow * DH + bc4) = nw;
        __syncthreads();
    }
}

// ---------------- fused layer kernel ----------------------------------------
// GATHER=false, KDIM=128 : out = act(X @ W + b)
// GATHER=true,  KDIM=256 : out = act([X | max_j Htab[idx[r][j]]] @ W + b)
// STATS : atomically accumulate per-column sum / sumsq of the activation.
template<int KDIM, bool RELU, bool GATHER, bool STATS>
__global__ void __launch_bounds__(256, 2)
layer_kernel(const float* __restrict__ X,
             const float* __restrict__ Htab,
             const int*   __restrict__ nidx,
             const float* __restrict__ W,
             const float* __restrict__ bias,
             float* __restrict__ out,
             float* __restrict__ gsum,
             float* __restrict__ gsq)
{
    extern __shared__ float smem[];
    constexpr int KPAD = KDIM + 4;
    float* As   = smem;                       // MT * KPAD
    float* Bs   = smem + MT * KPAD;           // 2 * KC * DH
    float* Sred = Bs + 2 * KC * DH;           // 2 * 16 * DH (STATS only)

    const int tid  = threadIdx.x;
    const int lane = tid & 31, warp = tid >> 5;
    const int tx   = tid & 15, ty   = tid >> 4;
    const int m0   = blockIdx.x * MT;

    // ---- Phase A: stage A tile (features + optional gather-max) ----
#pragma unroll
    for (int q = 0; q < MT / 8; ++q) {
        int lr = warp * (MT / 8) + q;
        int r  = m0 + lr; if (r >= NN) r = NN - 1;   // clamp (dup rows benign)

        float4 f = *(const float4*)(X + (size_t)r * DH + lane * 4);
        *(float4*)(As + lr * KPAD + lane * 4) = f;

        if (GATHER) {
            const int* nb = nidx + r * S_NEI;
            float4 m = make_float4(-1e30f, -1e30f, -1e30f, -1e30f);
#pragma unroll
            for (int j = 0; j < S_NEI; ++j) {
                int id = __ldg(nb + j);
                float4 v = *(const float4*)(Htab + (size_t)id * DH + lane * 4);
                m.x = fmaxf(m.x, v.x); m.y = fmaxf(m.y, v.y);
                m.z = fmaxf(m.z, v.z); m.w = fmaxf(m.w, v.w);
            }
            *(float4*)(As + lr * KPAD + DH + lane * 4) = m;
        }
    }

    float bcol[8];
#pragma unroll
    for (int j = 0; j < 8; ++j) bcol[j] = bias[tx * 8 + j];

    float acc[4][8];
#pragma unroll
    for (int i = 0; i < 4; ++i)
#pragma unroll
        for (int j = 0; j < 8; ++j) acc[i][j] = 0.f;

    gemm_acc<KDIM>(As, Bs, W, tid, acc);

    // ---- Epilogue ----
    float ps[8], pq[8];
    if (STATS) {
#pragma unroll
        for (int j = 0; j < 8; ++j) { ps[j] = 0.f; pq[j] = 0.f; }
    }
#pragma unroll
    for (int i = 0; i < 4; ++i) {
        int r = m0 + ty * 4 + i;
        if (r < NN) {
            float v[8];
#pragma unroll
            for (int j = 0; j < 8; ++j) {
                float t = acc[i][j] + bcol[j];
                if (RELU) t = fmaxf(t, 0.f);
                v[j] = t;
                if (STATS) { ps[j] += t; pq[j] += t * t; }
            }
            float4 o0 = make_float4(v[0], v[1], v[2], v[3]);
            float4 o1 = make_float4(v[4], v[5], v[6], v[7]);
            *(float4*)(out + (size_t)r * DH + tx * 8)     = o0;
            *(float4*)(out + (size_t)r * DH + tx * 8 + 4) = o1;
        }
    }

    if (STATS) {
#pragma unroll
        for (int j = 0; j < 8; ++j) {
            Sred[ty * DH + tx * 8 + j]           = ps[j];
            Sred[16 * DH + ty * DH + tx * 8 + j] = pq[j];
        }
        __syncthreads();
        if (tid < DH) {
            float s = 0.f, q = 0.f;
#pragma unroll
            for (int t2 = 0; t2 < 16; ++t2) {
                s += Sred[t2 * DH + tid];
                q += Sred[16 * DH + t2 * DH + tid];
            }
            atomicAdd(gsum + tid, s);
            atomicAdd(gsq + tid, q);
        }
    }
}

// ---------------- BN + row-norm + GEMM (layer-2 aggregator transform) -------
__global__ void __launch_bounds__(256, 2)
bn_rownorm_gemm_kernel(const float* __restrict__ X1,
                       const float* __restrict__ bn,
                       const float* __restrict__ W,
                       const float* __restrict__ bias,
                       float* __restrict__ xn,
                       float* __restrict__ h2)
{
    extern __shared__ float smem[];
    constexpr int KPAD = DH + 4;
    float* As = smem;
    float* Bs = smem + MT * KPAD;

    const int tid  = threadIdx.x;
    const int lane = tid & 31, warp = tid >> 5;
    const int tx   = tid & 15, ty   = tid >> 4;
    const int m0   = blockIdx.x * MT;

    float4 sc = *(const float4*)(bn + lane * 4);
    float4 sh = *(const float4*)(bn + DH + lane * 4);

#pragma unroll
    for (int q = 0; q < MT / 8; ++q) {
        int lr = warp * (MT / 8) + q;
        int r  = m0 + lr; if (r >= NN) r = NN - 1;
        float4 v = *(const float4*)(X1 + (size_t)r * DH + lane * 4);
        v.x = fmaf(v.x, sc.x, sh.x);
        v.y = fmaf(v.y, sc.y, sh.y);
        v.z = fmaf(v.z, sc.z, sh.z);
        v.w = fmaf(v.w, sc.w, sh.w);
        float ss = v.x * v.x + v.y * v.y + v.z * v.z + v.w * v.w;
#pragma unroll
        for (int o = 16; o; o >>= 1) ss += __shfl_xor_sync(0xffffffffu, ss, o);
        float inv = 1.f / (sqrtf(ss) + 1e-6f);
        v.x *= inv; v.y *= inv; v.z *= inv; v.w *= inv;
        *(float4*)(As + lr * KPAD + lane * 4) = v;
        *(float4*)(xn + (size_t)r * DH + lane * 4) = v;  // clamped dups write same value
    }

    float bcol[8];
#pragma unroll
    for (int j = 0; j < 8; ++j) bcol[j] = bias[tx * 8 + j];

    float acc[4][8];
#pragma unroll
    for (int i = 0; i < 4; ++i)
#pragma unroll
        for (int j = 0; j < 8; ++j) acc[i][j] = 0.f;

    gemm_acc<DH>(As, Bs, W, tid, acc);

#pragma unroll
    for (int i = 0; i < 4; ++i) {
        int r = m0 + ty * 4 + i;
        if (r < NN) {
            float v[8];
#pragma unroll
            for (int j = 0; j < 8; ++j)
                v[j] = fmaxf(acc[i][j] + bcol[j], 0.f);
            float4 o0 = make_float4(v[0], v[1], v[2], v[3]);
            float4 o1 = make_float4(v[4], v[5], v[6], v[7]);
            *(float4*)(h2 + (size_t)r * DH + tx * 8)     = o0;
            *(float4*)(h2 + (size_t)r * DH + tx * 8 + 4) = o1;
        }
    }
}

// ---------------- host launch ------------------------------------------------
extern "C" void kernel_launch(void* const* d_in, const int* in_sizes, int n_in,
                              void* d_out, int out_size)
{
    const float* features = (const float*)d_in[0];
    const int*   idx1     = (const int*)  d_in[1];
    const int*   idx2     = (const int*)  d_in[2];
    const float* agg1_W   = (const float*)d_in[3];
    const float* agg1_b   = (const float*)d_in[4];
    const float* fc1_W    = (const float*)d_in[5];
    const float* fc1_b    = (const float*)d_in[6];
    const float* agg2_W   = (const float*)d_in[7];
    const float* agg2_b   = (const float*)d_in[8];
    const float* fc2_W    = (const float*)d_in[9];
    const float* fc2_b    = (const float*)d_in[10];
    const float* gamma    = (const float*)d_in[11];
    const float* beta     = (const float*)d_in[12];
    float* out = (float*)d_out;

    void *h1, *x1, *xn, *h2, *gsum, *gsq, *bnp;
    cudaGetSymbolAddress(&h1,   g_h1);
    cudaGetSymbolAddress(&x1,   g_x1);
    cudaGetSymbolAddress(&xn,   g_xn);
    cudaGetSymbolAddress(&h2,   g_h2);
    cudaGetSymbolAddress(&gsum, g_sum);
    cudaGetSymbolAddress(&gsq,  g_sq);
    cudaGetSymbolAddress(&bnp,  g_bn);

    const int sm128  = (MT * (DH + 4)  + 2 * KC * DH) * (int)sizeof(float);            // 41,984 B
    const int sm256  = (MT * (256 + 4) + 2 * KC * DH) * (int)sizeof(float);            // 74,752 B
    const int sm256s = sm256 + 2 * 16 * DH * (int)sizeof(float);                       // 91,136 B

    cudaFuncSetAttribute((const void*)layer_kernel<128, true,  false, false>,
                         cudaFuncAttributeMaxDynamicSharedMemorySize, sm128);
    cudaFuncSetAttribute((const void*)layer_kernel<256, true,  true,  true>,
                         cudaFuncAttributeMaxDynamicSharedMemorySize, sm256s);
    cudaFuncSetAttribute((const void*)layer_kernel<256, false, true,  false>,
                         cudaFuncAttributeMaxDynamicSharedMemorySize, sm256);
    cudaFuncSetAttribute((const void*)bn_rownorm_gemm_kernel,
                         cudaFuncAttributeMaxDynamicSharedMemorySize, sm128);

    // K0: reset BN accumulators (scratch persists across graph replays)
    zero_stats_kernel<<<1, DH>>>((float*)gsum, (float*)gsq);

    // K1: h1 = relu(F @ agg1_W + agg1_b)
    layer_kernel<128, true, false, false><<<GRID, 256, sm128>>>(
        features, nullptr, nullptr, agg1_W, agg1_b, (float*)h1, nullptr, nullptr);

    // K2: x1 = relu([F | max_j h1[idx1]] @ fc1_W + fc1_b), accumulate BN stats
    layer_kernel<256, true, true, true><<<GRID, 256, sm256s>>>(
        features, (const float*)h1, idx1, fc1_W, fc1_b, (float*)x1,
        (float*)gsum, (float*)gsq);

    // K3: BN scale/shift
    bn_finalize_kernel<<<1, DH>>>((const float*)gsum, (const float*)gsq,
                                  gamma, beta, (float*)bnp);

    // K4: xn = rownorm(BN(x1)); h2 = relu(xn @ agg2_W + agg2_b)
    bn_rownorm_gemm_kernel<<<GRID, 256, sm128>>>(
        (const float*)x1, (const float*)bnp, agg2_W, agg2_b,
        (float*)xn, (float*)h2);

    // K5: out = [xn | max_j h2[idx2]] @ fc2_W + fc2_b
    layer_kernel<256, false, true, false><<<GRID, 256, sm256>>>(
        (const float*)xn, (const float*)h2, idx2, fc2_W, fc2_b, out,
        nullptr, nullptr);
}

// round 4
// speedup vs baseline: 2.2501x; 2.2501x over previous
#include <cuda_runtime.h>
#include <math.h>
#include <stdint.h>

// Problem constants
#define NN    50000
#define DH    128
#define S_NEI 25
#define MT    64                     // rows per CTA tile
#define KC    16                     // K-chunk for B double buffering
#define BPAD  136                    // padded B row (128 + 8) -> conflict-free frags
#define GRID  ((NN + MT - 1) / MT)   // 782

// ---------------- scratch (device globals; no allocation allowed) -----------
__device__ float g_h1[(size_t)NN * DH];
__device__ float g_x1[(size_t)NN * DH];
__device__ float g_xn[(size_t)NN * DH];
__device__ float g_h2[(size_t)NN * DH];
__device__ float g_sum[DH];
__device__ float g_sq[DH];
__device__ float g_bn[2 * DH];

// ---------------- tiny kernels ----------------------------------------------
__global__ void zero_stats_kernel(float* gsum, float* gsq) {
    gsum[threadIdx.x] = 0.f;
    gsq[threadIdx.x]  = 0.f;
}

__global__ void bn_finalize_kernel(const float* __restrict__ gsum,
                                   const float* __restrict__ gsq,
                                   const float* __restrict__ gamma,
                                   const float* __restrict__ beta,
                                   float* __restrict__ bn) {
    int c = threadIdx.x;
    const float invN = 1.f / (float)NN;
    float mean  = gsum[c] * invN;
    float var   = gsq[c] * invN - mean * mean;
    float rstd  = rsqrtf(var + 1e-5f);
    float scale = rstd * gamma[c];
    bn[c]      = scale;
    bn[DH + c] = beta[c] - mean * scale;
}

// ---------------- tf32 helpers ------------------------------------------------
__device__ __forceinline__ uint32_t f2tf32(float f) {
    uint32_t r;
    asm("cvt.rna.tf32.f32 %0, %1;" : "=r"(r) : "f"(f));
    return r;
}
__device__ __forceinline__ uint4 f4tf32(float4 v) {
    uint4 r;
    r.x = f2tf32(v.x); r.y = f2tf32(v.y); r.z = f2tf32(v.z); r.w = f2tf32(v.w);
    return r;
}

__device__ __forceinline__ void mma_tf32(float* c, const uint32_t* a,
                                         const uint32_t* b) {
    asm volatile(
        "mma.sync.aligned.m16n8k8.row.col.f32.tf32.tf32.f32 "
        "{%0,%1,%2,%3}, {%4,%5,%6,%7}, {%8,%9}, {%0,%1,%2,%3};\n"
        : "+f"(c[0]), "+f"(c[1]), "+f"(c[2]), "+f"(c[3])
        : "r"(a[0]), "r"(a[1]), "r"(a[2]), "r"(a[3]), "r"(b[0]), "r"(b[1]));
}

// ---------------- shared tensor-core GEMM core --------------------------------
// Computes a MT(64) x DH(128) tile: acc[mi 2][ni 4][4] per thread.
// 256 threads = 8 warps laid out 2(M) x 4(N); warp tile 32x32.
// As: tf32, row stride KPAD = KDIM+4 (bank-conflict-free A frags).
// Bs: two KC x BPAD tf32 buffers, streamed from W (KDIM x 128, row-major).
// Contains the barrier that publishes As (callers must NOT sync first).
template<int KDIM>
__device__ __forceinline__ void gemm_mma(const uint32_t* __restrict__ As,
                                         uint32_t* __restrict__ Bs,
                                         const float* __restrict__ W,
                                         int tid, float acc[2][4][4])
{
    constexpr int KPAD = KDIM + 4;
    constexpr int NKC  = KDIM / KC;
    const int gid = (tid & 31) >> 2;  // 0..7
    const int tig = tid & 3;          // 0..3
    const int wm  = (tid >> 5) >> 2;  // 0..1
    const int wn  = (tid >> 5) & 3;   // 0..3

    // stage B chunk 0 (16 x 128 floats = 512 float4; 2 per thread)
    {
        int f0 = tid, f1 = tid + 256;
        float4 v0 = *(const float4*)(W + (f0 >> 5) * DH + (f0 & 31) * 4);
        float4 v1 = *(const float4*)(W + (f1 >> 5) * DH + (f1 & 31) * 4);
        *(uint4*)(Bs + (f0 >> 5) * BPAD + (f0 & 31) * 4) = f4tf32(v0);
        *(uint4*)(Bs + (f1 >> 5) * BPAD + (f1 & 31) * 4) = f4tf32(v1);
    }
    __syncthreads();  // publishes As + Bs[0]

    for (int kc = 0; kc < NKC; ++kc) {
        float4 nv0, nv1;
        if (kc + 1 < NKC) {
            const float* Wn = W + (kc + 1) * KC * DH;
            int f0 = tid, f1 = tid + 256;
            nv0 = *(const float4*)(Wn + (f0 >> 5) * DH + (f0 & 31) * 4);
            nv1 = *(const float4*)(Wn + (f1 >> 5) * DH + (f1 & 31) * 4);
        }
        const uint32_t* B0 = Bs + (kc & 1) * (KC * BPAD);

#pragma unroll
        for (int k8 = 0; k8 < KC / 8; ++k8) {
            const int kA = kc * KC + k8 * 8 + tig;
            uint32_t a[2][4];
#pragma unroll
            for (int mi = 0; mi < 2; ++mi) {
                const uint32_t* ap = As + (wm * 32 + mi * 16 + gid) * KPAD + kA;
                a[mi][0] = ap[0];
                a[mi][1] = ap[8 * KPAD];
                a[mi][2] = ap[4];
                a[mi][3] = ap[8 * KPAD + 4];
            }
            uint32_t b[4][2];
#pragma unroll
            for (int ni = 0; ni < 4; ++ni) {
                const uint32_t* bp = B0 + (k8 * 8 + tig) * BPAD
                                        + wn * 32 + ni * 8 + gid;
                b[ni][0] = bp[0];
                b[ni][1] = bp[4 * BPAD];
            }
#pragma unroll
            for (int mi = 0; mi < 2; ++mi)
#pragma unroll
                for (int ni = 0; ni < 4; ++ni)
                    mma_tf32(acc[mi][ni], a[mi], b[ni]);
        }

        if (kc + 1 < NKC) {
            uint32_t* Bn = Bs + ((kc + 1) & 1) * (KC * BPAD);
            int f0 = tid, f1 = tid + 256;
            *(uint4*)(Bn + (f0 >> 5) * BPAD + (f0 & 31) * 4) = f4tf32(nv0);
            *(uint4*)(Bn + (f1 >> 5) * BPAD + (f1 & 31) * 4) = f4tf32(nv1);
        }
        __syncthreads();
    }
}

// ---------------- fused layer kernel ------------------------------------------
// GATHER=false, KDIM=128 : out = act(X @ W + b)
// GATHER=true,  KDIM=256 : out = act([X | max_j Htab[idx[r][j]]] @ W + b)
// STATS : accumulate per-column sum / sumsq of the activation into gsum/gsq.
template<int KDIM, bool RELU, bool GATHER, bool STATS>
__global__ void __launch_bounds__(256, 2)
layer_kernel(const float* __restrict__ X,
             const float* __restrict__ Htab,
             const int*   __restrict__ nidx,
             const float* __restrict__ W,
             const float* __restrict__ bias,
             float* __restrict__ out,
             float* __restrict__ gsum,
             float* __restrict__ gsq)
{
    extern __shared__ uint32_t smem[];
    constexpr int KPAD = KDIM + 4;
    uint32_t* As = smem;                              // MT * KPAD
    uint32_t* Bs = smem + MT * KPAD;                  // 2 * KC * BPAD
    float*  Sst  = (float*)(Bs + 2 * KC * BPAD);      // 256 floats (STATS)

    const int tid  = threadIdx.x;
    const int lane = tid & 31, wrp = tid >> 5;
    const int gid  = lane >> 2, tig = lane & 3;
    const int wm   = wrp >> 2,  wn  = wrp & 3;
    const int m0   = blockIdx.x * MT;

    if (STATS) Sst[tid] = 0.f;

    // ---- Phase A: stage A tile (features + optional gather-max), tf32 ----
#pragma unroll
    for (int q = 0; q < MT / 8; ++q) {
        int lr = wrp * (MT / 8) + q;
        int r  = m0 + lr; if (r >= NN) r = NN - 1;   // clamp (dup rows benign)

        float4 f = *(const float4*)(X + (size_t)r * DH + lane * 4);
        *(uint4*)(As + lr * KPAD + lane * 4) = f4tf32(f);

        if (GATHER) {
            const int* nb = nidx + r * S_NEI;
            float4 m = make_float4(-1e30f, -1e30f, -1e30f, -1e30f);
#pragma unroll
            for (int j = 0; j < S_NEI; ++j) {
                int id = __ldg(nb + j);
                float4 v = *(const float4*)(Htab + (size_t)id * DH + lane * 4);
                m.x = fmaxf(m.x, v.x); m.y = fmaxf(m.y, v.y);
                m.z = fmaxf(m.z, v.z); m.w = fmaxf(m.w, v.w);
            }
            *(uint4*)(As + lr * KPAD + DH + lane * 4) = f4tf32(m);
        }
    }

    float2 bb[4];
#pragma unroll
    for (int ni = 0; ni < 4; ++ni)
        bb[ni] = *(const float2*)(bias + wn * 32 + ni * 8 + 2 * tig);

    float acc[2][4][4];
#pragma unroll
    for (int mi = 0; mi < 2; ++mi)
#pragma unroll
        for (int ni = 0; ni < 4; ++ni)
#pragma unroll
            for (int c = 0; c < 4; ++c) acc[mi][ni][c] = 0.f;

    gemm_mma<KDIM>(As, Bs, W, tid, acc);

    // ---- Epilogue ----
    float ps[8], pq[8];
    if (STATS) {
#pragma unroll
        for (int j = 0; j < 8; ++j) { ps[j] = 0.f; pq[j] = 0.f; }
    }
#pragma unroll
    for (int mi = 0; mi < 2; ++mi) {
#pragma unroll
        for (int h = 0; h < 2; ++h) {
            int r = m0 + wm * 32 + mi * 16 + h * 8 + gid;
            if (r < NN) {
#pragma unroll
                for (int ni = 0; ni < 4; ++ni) {
                    float x0 = acc[mi][ni][h * 2 + 0] + bb[ni].x;
                    float x1 = acc[mi][ni][h * 2 + 1] + bb[ni].y;
                    if (RELU) { x0 = fmaxf(x0, 0.f); x1 = fmaxf(x1, 0.f); }
                    if (STATS) {
                        ps[ni * 2]     += x0; pq[ni * 2]     += x0 * x0;
                        ps[ni * 2 + 1] += x1; pq[ni * 2 + 1] += x1 * x1;
                    }
                    *(float2*)(out + (size_t)r * DH + wn * 32 + ni * 8 + 2 * tig)
                        = make_float2(x0, x1);
                }
            }
        }
    }

    if (STATS) {
        // reduce over gid (lanes 4 apart share tig)
#pragma unroll
        for (int j = 0; j < 8; ++j) {
#pragma unroll
            for (int o = 16; o >= 4; o >>= 1) {
                ps[j] += __shfl_xor_sync(0xffffffffu, ps[j], o);
                pq[j] += __shfl_xor_sync(0xffffffffu, pq[j], o);
            }
        }
        if (gid == 0) {
#pragma unroll
            for (int ni = 0; ni < 4; ++ni) {
                int c = wn * 32 + ni * 8 + 2 * tig;
                atomicAdd(Sst + c,           ps[ni * 2]);
                atomicAdd(Sst + c + 1,       ps[ni * 2 + 1]);
                atomicAdd(Sst + 128 + c,     pq[ni * 2]);
                atomicAdd(Sst + 128 + c + 1, pq[ni * 2 + 1]);
            }
        }
        __syncthreads();
        if (tid < DH) {
            atomicAdd(gsum + tid, Sst[tid]);
            atomicAdd(gsq + tid,  Sst[128 + tid]);
        }
    }
}

// ---------------- BN + row-norm + GEMM (layer-2 aggregator transform) ---------
__global__ void __launch_bounds__(256, 2)
bn_rownorm_gemm_kernel(const float* __restrict__ X1,
                       const float* __restrict__ bn,
                       const float* __restrict__ W,
                       const float* __restrict__ bias,
                       float* __restrict__ xn,
                       float* __restrict__ h2)
{
    extern __shared__ uint32_t smem[];
    constexpr int KPAD = DH + 4;
    uint32_t* As = smem;
    uint32_t* Bs = smem + MT * KPAD;

    const int tid  = threadIdx.x;
    const int lane = tid & 31, wrp = tid >> 5;
    const int gid  = lane >> 2, tig = lane & 3;
    const int wm   = wrp >> 2,  wn  = wrp & 3;
    const int m0   = blockIdx.x * MT;

    float4 sc = *(const float4*)(bn + lane * 4);
    float4 sh = *(const float4*)(bn + DH + lane * 4);

#pragma unroll
    for (int q = 0; q < MT / 8; ++q) {
        int lr = wrp * (MT / 8) + q;
        int r  = m0 + lr; if (r >= NN) r = NN - 1;
        float4 v = *(const float4*)(X1 + (size_t)r * DH + lane * 4);
        v.x = fmaf(v.x, sc.x, sh.x);
        v.y = fmaf(v.y, sc.y, sh.y);
        v.z = fmaf(v.z, sc.z, sh.z);
        v.w = fmaf(v.w, sc.w, sh.w);
        float ss = v.x * v.x + v.y * v.y + v.z * v.z + v.w * v.w;
#pragma unroll
        for (int o = 16; o; o >>= 1) ss += __shfl_xor_sync(0xffffffffu, ss, o);
        float inv = 1.f / (sqrtf(ss) + 1e-6f);
        v.x *= inv; v.y *= inv; v.z *= inv; v.w *= inv;
        *(uint4*)(As + lr * KPAD + lane * 4) = f4tf32(v);
        *(float4*)(xn + (size_t)r * DH + lane * 4) = v;  // dup rows write same value
    }

    float2 bb[4];
#pragma unroll
    for (int ni = 0; ni < 4; ++ni)
        bb[ni] = *(const float2*)(bias + wn * 32 + ni * 8 + 2 * tig);

    float acc[2][4][4];
#pragma unroll
    for (int mi = 0; mi < 2; ++mi)
#pragma unroll
        for (int ni = 0; ni < 4; ++ni)
#pragma unroll
            for (int c = 0; c < 4; ++c) acc[mi][ni][c] = 0.f;

    gemm_mma<DH>(As, Bs, W, tid, acc);

#pragma unroll
    for (int mi = 0; mi < 2; ++mi) {
#pragma unroll
        for (int h = 0; h < 2; ++h) {
            int r = m0 + wm * 32 + mi * 16 + h * 8 + gid;
            if (r < NN) {
#pragma unroll
                for (int ni = 0; ni < 4; ++ni) {
                    float x0 = fmaxf(acc[mi][ni][h * 2 + 0] + bb[ni].x, 0.f);
                    float x1 = fmaxf(acc[mi][ni][h * 2 + 1] + bb[ni].y, 0.f);
                    *(float2*)(h2 + (size_t)r * DH + wn * 32 + ni * 8 + 2 * tig)
                        = make_float2(x0, x1);
                }
            }
        }
    }
}

// ---------------- host launch --------------------------------------------------
extern "C" void kernel_launch(void* const* d_in, const int* in_sizes, int n_in,
                              void* d_out, int out_size)
{
    const float* features = (const float*)d_in[0];
    const int*   idx1     = (const int*)  d_in[1];
    const int*   idx2     = (const int*)  d_in[2];
    const float* agg1_W   = (const float*)d_in[3];
    const float* agg1_b   = (const float*)d_in[4];
    const float* fc1_W    = (const float*)d_in[5];
    const float* fc1_b    = (const float*)d_in[6];
    const float* agg2_W   = (const float*)d_in[7];
    const float* agg2_b   = (const float*)d_in[8];
    const float* fc2_W    = (const float*)d_in[9];
    const float* fc2_b    = (const float*)d_in[10];
    const float* gamma    = (const float*)d_in[11];
    const float* beta     = (const float*)d_in[12];
    float* out = (float*)d_out;

    void *h1, *x1, *xn, *h2, *gsum, *gsq, *bnp;
    cudaGetSymbolAddress(&h1,   g_h1);
    cudaGetSymbolAddress(&x1,   g_x1);
    cudaGetSymbolAddress(&xn,   g_xn);
    cudaGetSymbolAddress(&h2,   g_h2);
    cudaGetSymbolAddress(&gsum, g_sum);
    cudaGetSymbolAddress(&gsq,  g_sq);
    cudaGetSymbolAddress(&bnp,  g_bn);

    const int smB    = 2 * KC * BPAD * (int)sizeof(uint32_t);                 // 17408
    const int sm128  = MT * (DH + 4)  * 4 + smB;                              // 51200
    const int sm256  = MT * (256 + 4) * 4 + smB;                              // 83968
    const int sm256s = sm256 + 256 * (int)sizeof(float);                      // 84992

    cudaFuncSetAttribute((const void*)layer_kernel<128, true,  false, false>,
                         cudaFuncAttributeMaxDynamicSharedMemorySize, sm128);
    cudaFuncSetAttribute((const void*)layer_kernel<256, true,  true,  true>,
                         cudaFuncAttributeMaxDynamicSharedMemorySize, sm256s);
    cudaFuncSetAttribute((const void*)layer_kernel<256, false, true,  false>,
                         cudaFuncAttributeMaxDynamicSharedMemorySize, sm256);
    cudaFuncSetAttribute((const void*)bn_rownorm_gemm_kernel,
                         cudaFuncAttributeMaxDynamicSharedMemorySize, sm128);

    // K0: reset BN accumulators (scratch persists across graph replays)
    zero_stats_kernel<<<1, DH>>>((float*)gsum, (float*)gsq);

    // K1: h1 = relu(F @ agg1_W + agg1_b)
    layer_kernel<128, true, false, false><<<GRID, 256, sm128>>>(
        features, nullptr, nullptr, agg1_W, agg1_b, (float*)h1, nullptr, nullptr);

    // K2: x1 = relu([F | max_j h1[idx1]] @ fc1_W + fc1_b), accumulate BN stats
    layer_kernel<256, true, true, true><<<GRID, 256, sm256s>>>(
        features, (const float*)h1, idx1, fc1_W, fc1_b, (float*)x1,
        (float*)gsum, (float*)gsq);

    // K3: BN scale/shift
    bn_finalize_kernel<<<1, DH>>>((const float*)gsum, (const float*)gsq,
                                  gamma, beta, (float*)bnp);

    // K4: xn = rownorm(BN(x1)); h2 = relu(xn @ agg2_W + agg2_b)
    bn_rownorm_gemm_kernel<<<GRID, 256, sm128>>>(
        (const float*)x1, (const float*)bnp, agg2_W, agg2_b,
        (float*)xn, (float*)h2);

    // K5: out = [xn | max_j h2[idx2]] @ fc2_W + fc2_b
    layer_kernel<256, false, true, false><<<GRID, 256, sm256>>>(
        (const float*)xn, (const float*)h2, idx2, fc2_W, fc2_b, out,
        nullptr, nullptr);
}

// round 5
// speedup vs baseline: 2.6147x; 1.1620x over previous
#include <cuda_runtime.h>
#include <cuda_fp16.h>
#include <math.h>
#include <stdint.h>

// Problem constants
#define NN    50000
#define DH    128
#define S_NEI 25
#define MT    64                     // rows per CTA tile
#define KC    16                     // K-chunk for B double buffering
#define BPAD  136                    // padded B row (128 + 8) -> conflict-free frags
#define GRID  ((NN + MT - 1) / MT)   // 782

// ---------------- scratch (device globals; no allocation allowed) -----------
__device__ __half g_h1[(size_t)NN * DH];   // fp16 gather table, layer 1
__device__ float  g_x1[(size_t)NN * DH];
__device__ float  g_xn[(size_t)NN * DH];
__device__ __half g_h2[(size_t)NN * DH];   // fp16 gather table, layer 2
__device__ float  g_sum[DH];
__device__ float  g_sq[DH];

// ---------------- tf32 helpers ------------------------------------------------
__device__ __forceinline__ uint32_t f2tf32(float f) {
    uint32_t r;
    asm("cvt.rna.tf32.f32 %0, %1;" : "=r"(r) : "f"(f));
    return r;
}
__device__ __forceinline__ uint4 f4tf32(float4 v) {
    uint4 r;
    r.x = f2tf32(v.x); r.y = f2tf32(v.y); r.z = f2tf32(v.z); r.w = f2tf32(v.w);
    return r;
}

__device__ __forceinline__ void mma_tf32(float* c, const uint32_t* a,
                                         const uint32_t* b) {
    asm volatile(
        "mma.sync.aligned.m16n8k8.row.col.f32.tf32.tf32.f32 "
        "{%0,%1,%2,%3}, {%4,%5,%6,%7}, {%8,%9}, {%0,%1,%2,%3};\n"
        : "+f"(c[0]), "+f"(c[1]), "+f"(c[2]), "+f"(c[3])
        : "r"(a[0]), "r"(a[1]), "r"(a[2]), "r"(a[3]), "r"(b[0]), "r"(b[1]));
}

// generic 2-value store (fp32 or fp16 output)
__device__ __forceinline__ void store2(float* p, float x0, float x1) {
    *(float2*)p = make_float2(x0, x1);
}
__device__ __forceinline__ void store2(__half* p, float x0, float x1) {
    *(__half2*)p = __floats2half2_rn(x0, x1);
}

// ---------------- shared tensor-core GEMM core --------------------------------
// MT(64) x DH(128) tile: acc[mi 2][ni 4][4] per thread; 8 warps = 2(M) x 4(N).
// As: tf32, row stride KPAD = KDIM+4. Bs: two KC x BPAD tf32 buffers.
// Contains the barrier publishing As (callers must NOT sync first).
template<int KDIM>
__device__ __forceinline__ void gemm_mma(const uint32_t* __restrict__ As,
                                         uint32_t* __restrict__ Bs,
                                         const float* __restrict__ W,
                                         int tid, float acc[2][4][4])
{
    constexpr int KPAD = KDIM + 4;
    constexpr int NKC  = KDIM / KC;
    const int gid = (tid & 31) >> 2;
    const int tig = tid & 3;
    const int wm  = (tid >> 5) >> 2;
    const int wn  = (tid >> 5) & 3;

    // stage B chunk 0
    {
        int f0 = tid, f1 = tid + 256;
        float4 v0 = *(const float4*)(W + (f0 >> 5) * DH + (f0 & 31) * 4);
        float4 v1 = *(const float4*)(W + (f1 >> 5) * DH + (f1 & 31) * 4);
        *(uint4*)(Bs + (f0 >> 5) * BPAD + (f0 & 31) * 4) = f4tf32(v0);
        *(uint4*)(Bs + (f1 >> 5) * BPAD + (f1 & 31) * 4) = f4tf32(v1);
    }
    __syncthreads();  // publishes As + Bs[0]

    for (int kc = 0; kc < NKC; ++kc) {
        float4 nv0, nv1;
        if (kc + 1 < NKC) {
            const float* Wn = W + (kc + 1) * KC * DH;
            int f0 = tid, f1 = tid + 256;
            nv0 = *(const float4*)(Wn + (f0 >> 5) * DH + (f0 & 31) * 4);
            nv1 = *(const float4*)(Wn + (f1 >> 5) * DH + (f1 & 31) * 4);
        }
        const uint32_t* B0 = Bs + (kc & 1) * (KC * BPAD);

#pragma unroll
        for (int k8 = 0; k8 < KC / 8; ++k8) {
            const int kA = kc * KC + k8 * 8 + tig;
            uint32_t a[2][4];
#pragma unroll
            for (int mi = 0; mi < 2; ++mi) {
                const uint32_t* ap = As + (wm * 32 + mi * 16 + gid) * KPAD + kA;
                a[mi][0] = ap[0];
                a[mi][1] = ap[8 * KPAD];
                a[mi][2] = ap[4];
                a[mi][3] = ap[8 * KPAD + 4];
            }
            uint32_t b[4][2];
#pragma unroll
            for (int ni = 0; ni < 4; ++ni) {
                const uint32_t* bp = B0 + (k8 * 8 + tig) * BPAD
                                        + wn * 32 + ni * 8 + gid;
                b[ni][0] = bp[0];
                b[ni][1] = bp[4 * BPAD];
            }
#pragma unroll
            for (int mi = 0; mi < 2; ++mi)
#pragma unroll
                for (int ni = 0; ni < 4; ++ni)
                    mma_tf32(acc[mi][ni], a[mi], b[ni]);
        }

        if (kc + 1 < NKC) {
            uint32_t* Bn = Bs + ((kc + 1) & 1) * (KC * BPAD);
            int f0 = tid, f1 = tid + 256;
            *(uint4*)(Bn + (f0 >> 5) * BPAD + (f0 & 31) * 4) = f4tf32(nv0);
            *(uint4*)(Bn + (f1 >> 5) * BPAD + (f1 & 31) * 4) = f4tf32(nv1);
        }
        __syncthreads();
    }
}

// ---------------- fused layer kernel ------------------------------------------
// GATHER=false, KDIM=128 : out = act(X @ W + b)
// GATHER=true,  KDIM=256 : out = act([X | max_j Htab16[idx[r][j]]] @ W + b)
// STATS : accumulate per-column sum / sumsq of the activation.
// ZERO  : block 0 resets gsum/gsq (for the following STATS kernel).
template<int KDIM, bool RELU, bool GATHER, bool STATS, bool ZERO, typename OUTT>
__global__ void __launch_bounds__(256, 2)
layer_kernel(const float*  __restrict__ X,
             const __half* __restrict__ Htab,
             const int*    __restrict__ nidx,
             const float*  __restrict__ W,
             const float*  __restrict__ bias,
             OUTT* __restrict__ out,
             float* __restrict__ gsum,
             float* __restrict__ gsq)
{
    extern __shared__ uint32_t smem[];
    constexpr int KPAD = KDIM + 4;
    uint32_t* As = smem;                              // MT * KPAD
    uint32_t* Bs = smem + MT * KPAD;                  // 2 * KC * BPAD
    float*  Sst  = (float*)(Bs + 2 * KC * BPAD);      // 256 floats (STATS)

    const int tid  = threadIdx.x;
    const int lane = tid & 31, wrp = tid >> 5;
    const int gid  = lane >> 2, tig = lane & 3;
    const int wm   = wrp >> 2,  wn  = wrp & 3;
    const int m0   = blockIdx.x * MT;

    if (ZERO && blockIdx.x == 0 && tid < DH) {
        gsum[tid] = 0.f;
        gsq[tid]  = 0.f;
    }
    if (STATS) Sst[tid] = 0.f;

    // ---- Phase A: stage A tile (features + optional fp16 gather-max) ----
#pragma unroll
    for (int q = 0; q < MT / 8; ++q) {
        int lr = wrp * (MT / 8) + q;
        int r  = m0 + lr; if (r >= NN) r = NN - 1;   // clamp (dup rows benign)

        float4 f = *(const float4*)(X + (size_t)r * DH + lane * 4);
        *(uint4*)(As + lr * KPAD + lane * 4) = f4tf32(f);

        if (GATHER) {
            const int* nb = nidx + r * S_NEI;
            __half2 mA = __float2half2_rn(0.f);  // values are post-relu (>= 0)
            __half2 mB = mA;
#pragma unroll
            for (int j = 0; j < S_NEI; ++j) {
                int id = __ldg(nb + j);
                uint2 v = *(const uint2*)(Htab + (size_t)id * DH + lane * 4);
                mA = __hmax2(mA, *(__half2*)&v.x);
                mB = __hmax2(mB, *(__half2*)&v.y);
            }
            float2 fA = __half22float2(mA), fB = __half22float2(mB);
            float4 m  = make_float4(fA.x, fA.y, fB.x, fB.y);
            *(uint4*)(As + lr * KPAD + DH + lane * 4) = f4tf32(m);
        }
    }

    float2 bb[4];
#pragma unroll
    for (int ni = 0; ni < 4; ++ni)
        bb[ni] = *(const float2*)(bias + wn * 32 + ni * 8 + 2 * tig);

    float acc[2][4][4];
#pragma unroll
    for (int mi = 0; mi < 2; ++mi)
#pragma unroll
        for (int ni = 0; ni < 4; ++ni)
#pragma unroll
            for (int c = 0; c < 4; ++c) acc[mi][ni][c] = 0.f;

    gemm_mma<KDIM>(As, Bs, W, tid, acc);

    // ---- Epilogue ----
    float ps[8], pq[8];
    if (STATS) {
#pragma unroll
        for (int j = 0; j < 8; ++j) { ps[j] = 0.f; pq[j] = 0.f; }
    }
#pragma unroll
    for (int mi = 0; mi < 2; ++mi) {
#pragma unroll
        for (int h = 0; h < 2; ++h) {
            int r = m0 + wm * 32 + mi * 16 + h * 8 + gid;
            if (r < NN) {
#pragma unroll
                for (int ni = 0; ni < 4; ++ni) {
                    float x0 = acc[mi][ni][h * 2 + 0] + bb[ni].x;
                    float x1 = acc[mi][ni][h * 2 + 1] + bb[ni].y;
                    if (RELU) { x0 = fmaxf(x0, 0.f); x1 = fmaxf(x1, 0.f); }
                    if (STATS) {
                        ps[ni * 2]     += x0; pq[ni * 2]     += x0 * x0;
                        ps[ni * 2 + 1] += x1; pq[ni * 2 + 1] += x1 * x1;
                    }
                    store2(out + (size_t)r * DH + wn * 32 + ni * 8 + 2 * tig,
                           x0, x1);
                }
            }
        }
    }

    if (STATS) {
#pragma unroll
        for (int j = 0; j < 8; ++j) {
#pragma unroll
            for (int o = 16; o >= 4; o >>= 1) {
                ps[j] += __shfl_xor_sync(0xffffffffu, ps[j], o);
                pq[j] += __shfl_xor_sync(0xffffffffu, pq[j], o);
            }
        }
        if (gid == 0) {
#pragma unroll
            for (int ni = 0; ni < 4; ++ni) {
                int c = wn * 32 + ni * 8 + 2 * tig;
                atomicAdd(Sst + c,           ps[ni * 2]);
                atomicAdd(Sst + c + 1,       ps[ni * 2 + 1]);
                atomicAdd(Sst + 128 + c,     pq[ni * 2]);
                atomicAdd(Sst + 128 + c + 1, pq[ni * 2 + 1]);
            }
        }
        __syncthreads();
        if (tid < DH) {
            atomicAdd(gsum + tid, Sst[tid]);
            atomicAdd(gsq + tid,  Sst[128 + tid]);
        }
    }
}

// ---------------- BN(finalize inline) + row-norm + GEMM -----------------------
__global__ void __launch_bounds__(256, 2)
bn_rownorm_gemm_kernel(const float* __restrict__ X1,
                       const float* __restrict__ gsum,
                       const float* __restrict__ gsq,
                       const float* __restrict__ gamma,
                       const float* __restrict__ beta,
                       const float* __restrict__ W,
                       const float* __restrict__ bias,
                       float*  __restrict__ xn,
                       __half* __restrict__ h2)
{
    extern __shared__ uint32_t smem[];
    constexpr int KPAD = DH + 4;
    uint32_t* As = smem;
    uint32_t* Bs = smem + MT * KPAD;

    const int tid  = threadIdx.x;
    const int lane = tid & 31, wrp = tid >> 5;
    const int gid  = lane >> 2, tig = lane & 3;
    const int wm   = wrp >> 2,  wn  = wrp & 3;
    const int m0   = blockIdx.x * MT;

    // inline BN finalize for this lane's 4 channels (lane*4 .. +3)
    float sc[4], sh[4];
    {
        const float invN = 1.f / (float)NN;
#pragma unroll
        for (int i = 0; i < 4; ++i) {
            int c = lane * 4 + i;
            float mean = __ldg(gsum + c) * invN;
            float var  = __ldg(gsq + c) * invN - mean * mean;
            float s    = rsqrtf(var + 1e-5f) * __ldg(gamma + c);
            sc[i] = s;
            sh[i] = __ldg(beta + c) - mean * s;
        }
    }

#pragma unroll
    for (int q = 0; q < MT / 8; ++q) {
        int lr = wrp * (MT / 8) + q;
        int r  = m0 + lr; if (r >= NN) r = NN - 1;
        float4 v = *(const float4*)(X1 + (size_t)r * DH + lane * 4);
        v.x = fmaf(v.x, sc[0], sh[0]);
        v.y = fmaf(v.y, sc[1], sh[1]);
        v.z = fmaf(v.z, sc[2], sh[2]);
        v.w = fmaf(v.w, sc[3], sh[3]);
        float ss = v.x * v.x + v.y * v.y + v.z * v.z + v.w * v.w;
#pragma unroll
        for (int o = 16; o; o >>= 1) ss += __shfl_xor_sync(0xffffffffu, ss, o);
        float inv = 1.f / (sqrtf(ss) + 1e-6f);
        v.x *= inv; v.y *= inv; v.z *= inv; v.w *= inv;
        *(uint4*)(As + lr * KPAD + lane * 4) = f4tf32(v);
        *(float4*)(xn + (size_t)r * DH + lane * 4) = v;  // dup rows write same value
    }

    float2 bb[4];
#pragma unroll
    for (int ni = 0; ni < 4; ++ni)
        bb[ni] = *(const float2*)(bias + wn * 32 + ni * 8 + 2 * tig);

    float acc[2][4][4];
#pragma unroll
    for (int mi = 0; mi < 2; ++mi)
#pragma unroll
        for (int ni = 0; ni < 4; ++ni)
#pragma unroll
            for (int c = 0; c < 4; ++c) acc[mi][ni][c] = 0.f;

    gemm_mma<DH>(As, Bs, W, tid, acc);

#pragma unroll
    for (int mi = 0; mi < 2; ++mi) {
#pragma unroll
        for (int h = 0; h < 2; ++h) {
            int r = m0 + wm * 32 + mi * 16 + h * 8 + gid;
            if (r < NN) {
#pragma unroll
                for (int ni = 0; ni < 4; ++ni) {
                    float x0 = fmaxf(acc[mi][ni][h * 2 + 0] + bb[ni].x, 0.f);
                    float x1 = fmaxf(acc[mi][ni][h * 2 + 1] + bb[ni].y, 0.f);
                    store2(h2 + (size_t)r * DH + wn * 32 + ni * 8 + 2 * tig,
                           x0, x1);
                }
            }
        }
    }
}

// ---------------- host launch --------------------------------------------------
extern "C" void kernel_launch(void* const* d_in, const int* in_sizes, int n_in,
                              void* d_out, int out_size)
{
    const float* features = (const float*)d_in[0];
    const int*   idx1     = (const int*)  d_in[1];
    const int*   idx2     = (const int*)  d_in[2];
    const float* agg1_W   = (const float*)d_in[3];
    const float* agg1_b   = (const float*)d_in[4];
    const float* fc1_W    = (const float*)d_in[5];
    const float* fc1_b    = (const float*)d_in[6];
    const float* agg2_W   = (const float*)d_in[7];
    const float* agg2_b   = (const float*)d_in[8];
    const float* fc2_W    = (const float*)d_in[9];
    const float* fc2_b    = (const float*)d_in[10];
    const float* gamma    = (const float*)d_in[11];
    const float* beta     = (const float*)d_in[12];
    float* out = (float*)d_out;

    void *h1, *x1, *xn, *h2, *gsum, *gsq;
    cudaGetSymbolAddress(&h1,   g_h1);
    cudaGetSymbolAddress(&x1,   g_x1);
    cudaGetSymbolAddress(&xn,   g_xn);
    cudaGetSymbolAddress(&h2,   g_h2);
    cudaGetSymbolAddress(&gsum, g_sum);
    cudaGetSymbolAddress(&gsq,  g_sq);

    const int smB    = 2 * KC * BPAD * (int)sizeof(uint32_t);   // 17408
    const int sm128  = MT * (DH + 4)  * 4 + smB;                // 51200
    const int sm256  = MT * (256 + 4) * 4 + smB;                // 83968
    const int sm256s = sm256 + 256 * (int)sizeof(float);        // 84992

    cudaFuncSetAttribute(
        (const void*)layer_kernel<128, true, false, false, true, __half>,
        cudaFuncAttributeMaxDynamicSharedMemorySize, sm128);
    cudaFuncSetAttribute(
        (const void*)layer_kernel<256, true, true, true, false, float>,
        cudaFuncAttributeMaxDynamicSharedMemorySize, sm256s);
    cudaFuncSetAttribute(
        (const void*)layer_kernel<256, false, true, false, false, float>,
        cudaFuncAttributeMaxDynamicSharedMemorySize, sm256);
    cudaFuncSetAttribute((const void*)bn_rownorm_gemm_kernel,
        cudaFuncAttributeMaxDynamicSharedMemorySize, sm128);

    // K1: h1 = relu(F @ agg1_W + b) -> fp16 table; block 0 zeroes BN stats
    layer_kernel<128, true, false, false, true, __half><<<GRID, 256, sm128>>>(
        features, nullptr, nullptr, agg1_W, agg1_b, (__half*)h1,
        (float*)gsum, (float*)gsq);

    // K2: x1 = relu([F | max_j h1[idx1]] @ fc1_W + b), accumulate BN stats
    layer_kernel<256, true, true, true, false, float><<<GRID, 256, sm256s>>>(
        features, (const __half*)h1, idx1, fc1_W, fc1_b, (float*)x1,
        (float*)gsum, (float*)gsq);

    // K3: xn = rownorm(BN(x1)); h2 = relu(xn @ agg2_W + b) -> fp16 table
    bn_rownorm_gemm_kernel<<<GRID, 256, sm128>>>(
        (const float*)x1, (const float*)gsum, (const float*)gsq, gamma, beta,
        agg2_W, agg2_b, (float*)xn, (__half*)h2);

    // K4: out = [xn | max_j h2[idx2]] @ fc2_W + b
    layer_kernel<256, false, true, false, false, float><<<GRID, 256, sm256>>>(
        (const float*)xn, (const __half*)h2, idx2, fc2_W, fc2_b, out,
        nullptr, nullptr);
}

// round 6
// speedup vs baseline: 2.6278x; 1.0050x over previous
#include <cuda_runtime.h>
#include <cuda_fp16.h>
#include <math.h>
#include <stdint.h>

// Problem constants
#define NN    50000
#define DH    128
#define S_NEI 25
#define MT    64                     // rows per CTA tile
#define KC    16                     // K-chunk for B double buffering
#define BPAD  136                    // padded B row (128 + 8) -> conflict-free frags
#define GRID  ((NN + MT - 1) / MT)   // 782

// ---------------- scratch (device globals; no allocation allowed) -----------
__device__ __half g_h1[(size_t)NN * DH];   // fp16 gather table, layer 1
__device__ float  g_x1[(size_t)NN * DH];
__device__ float  g_xn[(size_t)NN * DH];
__device__ __half g_h2[(size_t)NN * DH];   // fp16 gather table, layer 2
__device__ float  g_sum[DH];
__device__ float  g_sq[DH];

// ---------------- tf32 helpers ------------------------------------------------
__device__ __forceinline__ uint32_t f2tf32(float f) {
    uint32_t r;
    asm("cvt.rna.tf32.f32 %0, %1;" : "=r"(r) : "f"(f));
    return r;
}
__device__ __forceinline__ uint4 f4tf32(float4 v) {
    uint4 r;
    r.x = f2tf32(v.x); r.y = f2tf32(v.y); r.z = f2tf32(v.z); r.w = f2tf32(v.w);
    return r;
}

__device__ __forceinline__ void mma_tf32(float* c, const uint32_t* a,
                                         const uint32_t* b) {
    asm volatile(
        "mma.sync.aligned.m16n8k8.row.col.f32.tf32.tf32.f32 "
        "{%0,%1,%2,%3}, {%4,%5,%6,%7}, {%8,%9}, {%0,%1,%2,%3};\n"
        : "+f"(c[0]), "+f"(c[1]), "+f"(c[2]), "+f"(c[3])
        : "r"(a[0]), "r"(a[1]), "r"(a[2]), "r"(a[3]), "r"(b[0]), "r"(b[1]));
}

// generic 2-value store (fp32 or fp16 output)
__device__ __forceinline__ void store2(float* p, float x0, float x1) {
    *(float2*)p = make_float2(x0, x1);
}
__device__ __forceinline__ void store2(__half* p, float x0, float x1) {
    *(__half2*)p = __floats2half2_rn(x0, x1);
}

// ---------------- shared tensor-core GEMM core --------------------------------
// MT(64) x DH(128) tile: acc[mi 2][ni 4][4] per thread; 8 warps = 2(M) x 4(N).
// As: tf32, row stride KPAD = KDIM+4. Bs: two KC x BPAD tf32 buffers.
// Contains the barrier publishing As (callers must NOT sync first).
template<int KDIM>
__device__ __forceinline__ void gemm_mma(const uint32_t* __restrict__ As,
                                         uint32_t* __restrict__ Bs,
                                         const float* __restrict__ W,
                                         int tid, float acc[2][4][4])
{
    constexpr int KPAD = KDIM + 4;
    constexpr int NKC  = KDIM / KC;
    const int gid = (tid & 31) >> 2;
    const int tig = tid & 3;
    const int wm  = (tid >> 5) >> 2;
    const int wn  = (tid >> 5) & 3;

    // stage B chunk 0
    {
        int f0 = tid, f1 = tid + 256;
        float4 v0 = *(const float4*)(W + (f0 >> 5) * DH + (f0 & 31) * 4);
        float4 v1 = *(const float4*)(W + (f1 >> 5) * DH + (f1 & 31) * 4);
        *(uint4*)(Bs + (f0 >> 5) * BPAD + (f0 & 31) * 4) = f4tf32(v0);
        *(uint4*)(Bs + (f1 >> 5) * BPAD + (f1 & 31) * 4) = f4tf32(v1);
    }
    __syncthreads();  // publishes As + Bs[0]

    for (int kc = 0; kc < NKC; ++kc) {
        float4 nv0, nv1;
        if (kc + 1 < NKC) {
            const float* Wn = W + (kc + 1) * KC * DH;
            int f0 = tid, f1 = tid + 256;
            nv0 = *(const float4*)(Wn + (f0 >> 5) * DH + (f0 & 31) * 4);
            nv1 = *(const float4*)(Wn + (f1 >> 5) * DH + (f1 & 31) * 4);
        }
        const uint32_t* B0 = Bs + (kc & 1) * (KC * BPAD);

#pragma unroll
        for (int k8 = 0; k8 < KC / 8; ++k8) {
            const int kA = kc * KC + k8 * 8 + tig;
            uint32_t a[2][4];
#pragma unroll
            for (int mi = 0; mi < 2; ++mi) {
                const uint32_t* ap = As + (wm * 32 + mi * 16 + gid) * KPAD + kA;
                a[mi][0] = ap[0];
                a[mi][1] = ap[8 * KPAD];
                a[mi][2] = ap[4];
                a[mi][3] = ap[8 * KPAD + 4];
            }
            uint32_t b[4][2];
#pragma unroll
            for (int ni = 0; ni < 4; ++ni) {
                const uint32_t* bp = B0 + (k8 * 8 + tig) * BPAD
                                        + wn * 32 + ni * 8 + gid;
                b[ni][0] = bp[0];
                b[ni][1] = bp[4 * BPAD];
            }
#pragma unroll
            for (int mi = 0; mi < 2; ++mi)
#pragma unroll
                for (int ni = 0; ni < 4; ++ni)
                    mma_tf32(acc[mi][ni], a[mi], b[ni]);
        }

        if (kc + 1 < NKC) {
            uint32_t* Bn = Bs + ((kc + 1) & 1) * (KC * BPAD);
            int f0 = tid, f1 = tid + 256;
            *(uint4*)(Bn + (f0 >> 5) * BPAD + (f0 & 31) * 4) = f4tf32(nv0);
            *(uint4*)(Bn + (f1 >> 5) * BPAD + (f1 & 31) * 4) = f4tf32(nv1);
        }
        __syncthreads();
    }
}

// ---------------- fused layer kernel ------------------------------------------
// GATHER=false, KDIM=128 : out = act(X @ W + b)
// GATHER=true,  KDIM=256 : out = act([X | max_j Htab16[idx[r][j]]] @ W + b)
// STATS : accumulate per-column sum / sumsq of the activation.
// ZERO  : block 0 resets gsum/gsq (for the following STATS kernel).
template<int KDIM, bool RELU, bool GATHER, bool STATS, bool ZERO, typename OUTT>
__global__ void __launch_bounds__(256, 2)
layer_kernel(const float*  __restrict__ X,
             const __half* __restrict__ Htab,
             const int*    __restrict__ nidx,
             const float*  __restrict__ W,
             const float*  __restrict__ bias,
             OUTT* __restrict__ out,
             float* __restrict__ gsum,
             float* __restrict__ gsq)
{
    extern __shared__ uint32_t smem[];
    constexpr int KPAD = KDIM + 4;
    uint32_t* As = smem;                              // MT * KPAD
    uint32_t* Bs = smem + MT * KPAD;                  // 2 * KC * BPAD
    float*  Sst  = (float*)(Bs + 2 * KC * BPAD);      // 256 floats (STATS)

    const int tid  = threadIdx.x;
    const int lane = tid & 31, wrp = tid >> 5;
    const int gid  = lane >> 2, tig = lane & 3;
    const int wm   = wrp >> 2,  wn  = wrp & 3;
    const int m0   = blockIdx.x * MT;

    if (ZERO && blockIdx.x == 0 && tid < DH) {
        gsum[tid] = 0.f;
        gsq[tid]  = 0.f;
    }
    if (STATS) Sst[tid] = 0.f;

    // ---- Phase A: stage A tile (features + optional fp16 gather-max) ----
#pragma unroll
    for (int q = 0; q < MT / 8; ++q) {
        int lr = wrp * (MT / 8) + q;
        int r  = m0 + lr; if (r >= NN) r = NN - 1;   // clamp (dup rows benign)

        float4 f = *(const float4*)(X + (size_t)r * DH + lane * 4);
        *(uint4*)(As + lr * KPAD + lane * 4) = f4tf32(f);

        if (GATHER) {
            const int* nb = nidx + r * S_NEI;
            __half2 mA = __float2half2_rn(0.f);  // values are post-relu (>= 0)
            __half2 mB = mA;
#pragma unroll
            for (int j = 0; j < S_NEI; ++j) {
                int id = __ldg(nb + j);
                uint2 v = *(const uint2*)(Htab + (size_t)id * DH + lane * 4);
                mA = __hmax2(mA, *(__half2*)&v.x);
                mB = __hmax2(mB, *(__half2*)&v.y);
            }
            float2 fA = __half22float2(mA), fB = __half22float2(mB);
            float4 m  = make_float4(fA.x, fA.y, fB.x, fB.y);
            *(uint4*)(As + lr * KPAD + DH + lane * 4) = f4tf32(m);
        }
    }

    float2 bb[4];
#pragma unroll
    for (int ni = 0; ni < 4; ++ni)
        bb[ni] = *(const float2*)(bias + wn * 32 + ni * 8 + 2 * tig);

    float acc[2][4][4];
#pragma unroll
    for (int mi = 0; mi < 2; ++mi)
#pragma unroll
        for (int ni = 0; ni < 4; ++ni)
#pragma unroll
            for (int c = 0; c < 4; ++c) acc[mi][ni][c] = 0.f;

    gemm_mma<KDIM>(As, Bs, W, tid, acc);

    // ---- Epilogue ----
    float ps[8], pq[8];
    if (STATS) {
#pragma unroll
        for (int j = 0; j < 8; ++j) { ps[j] = 0.f; pq[j] = 0.f; }
    }
#pragma unroll
    for (int mi = 0; mi < 2; ++mi) {
#pragma unroll
        for (int h = 0; h < 2; ++h) {
            int r = m0 + wm * 32 + mi * 16 + h * 8 + gid;
            if (r < NN) {
#pragma unroll
                for (int ni = 0; ni < 4; ++ni) {
                    float x0 = acc[mi][ni][h * 2 + 0] + bb[ni].x;
                    float x1 = acc[mi][ni][h * 2 + 1] + bb[ni].y;
                    if (RELU) { x0 = fmaxf(x0, 0.f); x1 = fmaxf(x1, 0.f); }
                    if (STATS) {
                        ps[ni * 2]     += x0; pq[ni * 2]     += x0 * x0;
                        ps[ni * 2 + 1] += x1; pq[ni * 2 + 1] += x1 * x1;
                    }
                    store2(out + (size_t)r * DH + wn * 32 + ni * 8 + 2 * tig,
                           x0, x1);
                }
            }
        }
    }

    if (STATS) {
#pragma unroll
        for (int j = 0; j < 8; ++j) {
#pragma unroll
            for (int o = 16; o >= 4; o >>= 1) {
                ps[j] += __shfl_xor_sync(0xffffffffu, ps[j], o);
                pq[j] += __shfl_xor_sync(0xffffffffu, pq[j], o);
            }
        }
        if (gid == 0) {
#pragma unroll
            for (int ni = 0; ni < 4; ++ni) {
                int c = wn * 32 + ni * 8 + 2 * tig;
                atomicAdd(Sst + c,           ps[ni * 2]);
                atomicAdd(Sst + c + 1,       ps[ni * 2 + 1]);
                atomicAdd(Sst + 128 + c,     pq[ni * 2]);
                atomicAdd(Sst + 128 + c + 1, pq[ni * 2 + 1]);
            }
        }
        __syncthreads();
        if (tid < DH) {
            atomicAdd(gsum + tid, Sst[tid]);
            atomicAdd(gsq + tid,  Sst[128 + tid]);
        }
    }
}

// ---------------- BN(finalize inline) + row-norm + GEMM -----------------------
__global__ void __launch_bounds__(256, 2)
bn_rownorm_gemm_kernel(const float* __restrict__ X1,
                       const float* __restrict__ gsum,
                       const float* __restrict__ gsq,
                       const float* __restrict__ gamma,
                       const float* __restrict__ beta,
                       const float* __restrict__ W,
                       const float* __restrict__ bias,
                       float*  __restrict__ xn,
                       __half* __restrict__ h2)
{
    extern __shared__ uint32_t smem[];
    constexpr int KPAD = DH + 4;
    uint32_t* As = smem;
    uint32_t* Bs = smem + MT * KPAD;

    const int tid  = threadIdx.x;
    const int lane = tid & 31, wrp = tid >> 5;
    const int gid  = lane >> 2, tig = lane & 3;
    const int wm   = wrp >> 2,  wn  = wrp & 3;
    const int m0   = blockIdx.x * MT;

    // inline BN finalize for this lane's 4 channels (lane*4 .. +3)
    float sc[4], sh[4];
    {
        const float invN = 1.f / (float)NN;
#pragma unroll
        for (int i = 0; i < 4; ++i) {
            int c = lane * 4 + i;
            float mean = __ldg(gsum + c) * invN;
            float var  = __ldg(gsq + c) * invN - mean * mean;
            float s    = rsqrtf(var + 1e-5f) * __ldg(gamma + c);
            sc[i] = s;
            sh[i] = __ldg(beta + c) - mean * s;
        }
    }

#pragma unroll
    for (int q = 0; q < MT / 8; ++q) {
        int lr = wrp * (MT / 8) + q;
        int r  = m0 + lr; if (r >= NN) r = NN - 1;
        float4 v = *(const float4*)(X1 + (size_t)r * DH + lane * 4);
        v.x = fmaf(v.x, sc[0], sh[0]);
        v.y = fmaf(v.y, sc[1], sh[1]);
        v.z = fmaf(v.z, sc[2], sh[2]);
        v.w = fmaf(v.w, sc[3], sh[3]);
        float ss = v.x * v.x + v.y * v.y + v.z * v.z + v.w * v.w;
#pragma unroll
        for (int o = 16; o; o >>= 1) ss += __shfl_xor_sync(0xffffffffu, ss, o);
        float inv = 1.f / (sqrtf(ss) + 1e-6f);
        v.x *= inv; v.y *= inv; v.z *= inv; v.w *= inv;
        *(uint4*)(As + lr * KPAD + lane * 4) = f4tf32(v);
        *(float4*)(xn + (size_t)r * DH + lane * 4) = v;  // dup rows write same value
    }

    float2 bb[4];
#pragma unroll
    for (int ni = 0; ni < 4; ++ni)
        bb[ni] = *(const float2*)(bias + wn * 32 + ni * 8 + 2 * tig);

    float acc[2][4][4];
#pragma unroll
    for (int mi = 0; mi < 2; ++mi)
#pragma unroll
        for (int ni = 0; ni < 4; ++ni)
#pragma unroll
            for (int c = 0; c < 4; ++c) acc[mi][ni][c] = 0.f;

    gemm_mma<DH>(As, Bs, W, tid, acc);

#pragma unroll
    for (int mi = 0; mi < 2; ++mi) {
#pragma unroll
        for (int h = 0; h < 2; ++h) {
            int r = m0 + wm * 32 + mi * 16 + h * 8 + gid;
            if (r < NN) {
#pragma unroll
                for (int ni = 0; ni < 4; ++ni) {
                    float x0 = fmaxf(acc[mi][ni][h * 2 + 0] + bb[ni].x, 0.f);
                    float x1 = fmaxf(acc[mi][ni][h * 2 + 1] + bb[ni].y, 0.f);
                    store2(h2 + (size_t)r * DH + wn * 32 + ni * 8 + 2 * tig,
                           x0, x1);
                }
            }
        }
    }
}

// ---------------- host launch --------------------------------------------------
extern "C" void kernel_launch(void* const* d_in, const int* in_sizes, int n_in,
                              void* d_out, int out_size)
{
    const float* features = (const float*)d_in[0];
    const int*   idx1     = (const int*)  d_in[1];
    const int*   idx2     = (const int*)  d_in[2];
    const float* agg1_W   = (const float*)d_in[3];
    const float* agg1_b   = (const float*)d_in[4];
    const float* fc1_W    = (const float*)d_in[5];
    const float* fc1_b    = (const float*)d_in[6];
    const float* agg2_W   = (const float*)d_in[7];
    const float* agg2_b   = (const float*)d_in[8];
    const float* fc2_W    = (const float*)d_in[9];
    const float* fc2_b    = (const float*)d_in[10];
    const float* gamma    = (const float*)d_in[11];
    const float* beta     = (const float*)d_in[12];
    float* out = (float*)d_out;

    void *h1, *x1, *xn, *h2, *gsum, *gsq;
    cudaGetSymbolAddress(&h1,   g_h1);
    cudaGetSymbolAddress(&x1,   g_x1);
    cudaGetSymbolAddress(&xn,   g_xn);
    cudaGetSymbolAddress(&h2,   g_h2);
    cudaGetSymbolAddress(&gsum, g_sum);
    cudaGetSymbolAddress(&gsq,  g_sq);

    const int smB    = 2 * KC * BPAD * (int)sizeof(uint32_t);   // 17408
    const int sm128  = MT * (DH + 4)  * 4 + smB;                // 51200
    const int sm256  = MT * (256 + 4) * 4 + smB;                // 83968
    const int sm256s = sm256 + 256 * (int)sizeof(float);        // 84992

    cudaFuncSetAttribute(
        (const void*)layer_kernel<128, true, false, false, true, __half>,
        cudaFuncAttributeMaxDynamicSharedMemorySize, sm128);
    cudaFuncSetAttribute(
        (const void*)layer_kernel<256, true, true, true, false, float>,
        cudaFuncAttributeMaxDynamicSharedMemorySize, sm256s);
    cudaFuncSetAttribute(
        (const void*)layer_kernel<256, false, true, false, false, float>,
        cudaFuncAttributeMaxDynamicSharedMemorySize, sm256);
    cudaFuncSetAttribute((const void*)bn_rownorm_gemm_kernel,
        cudaFuncAttributeMaxDynamicSharedMemorySize, sm128);

    // K1: h1 = relu(F @ agg1_W + b) -> fp16 table; block 0 zeroes BN stats
    layer_kernel<128, true, false, false, true, __half><<<GRID, 256, sm128>>>(
        features, nullptr, nullptr, agg1_W, agg1_b, (__half*)h1,
        (float*)gsum, (float*)gsq);

    // K2: x1 = relu([F | max_j h1[idx1]] @ fc1_W + b), accumulate BN stats
    layer_kernel<256, true, true, true, false, float><<<GRID, 256, sm256s>>>(
        features, (const __half*)h1, idx1, fc1_W, fc1_b, (float*)x1,
        (float*)gsum, (float*)gsq);

    // K3: xn = rownorm(BN(x1)); h2 = relu(xn @ agg2_W + b) -> fp16 table
    bn_rownorm_gemm_kernel<<<GRID, 256, sm128>>>(
        (const float*)x1, (const float*)gsum, (const float*)gsq, gamma, beta,
        agg2_W, agg2_b, (float*)xn, (__half*)h2);

    // K4: out = [xn | max_j h2[idx2]] @ fc2_W + b
    layer_kernel<256, false, true, false, false, float><<<GRID, 256, sm256>>>(
        (const float*)xn, (const __half*)h2, idx2, fc2_W, fc2_b, out,
        nullptr, nullptr);
}